// round 1
// baseline (speedup 1.0000x reference)
#include <cuda_runtime.h>
#include <cuda_bf16.h>
#include <cstdint>

#define N_NODES 100000
#define N_EDGES 3200000
#define IN_F 512
#define OUT_F 256

typedef unsigned long long u64;

// ---------------- scratch (device globals; no runtime allocation) ------------
__device__ __align__(16) float g_support[(size_t)N_NODES * OUT_F]; // 102.4 MB
__device__ int   g_count[N_NODES];
__device__ int   g_start[N_NODES + 1];
__device__ int   g_col[N_EDGES];
__device__ float g_val[N_EDGES];

// ---------------- packed fp32x2 helpers (Blackwell-only FFMA2 path) ----------
__device__ __forceinline__ u64 fma2(u64 a, u64 b, u64 c) {
    u64 d;
    asm("fma.rn.f32x2 %0, %1, %2, %3;" : "=l"(d) : "l"(a), "l"(b), "l"(c));
    return d;
}
__device__ __forceinline__ u64 dup2(float x) {
    u64 r; asm("mov.b64 %0, {%1, %1};" : "=l"(r) : "f"(x)); return r;
}
__device__ __forceinline__ void unpack2(u64 v, float& lo, float& hi) {
    asm("mov.b64 {%0, %1}, %2;" : "=f"(lo), "=f"(hi) : "l"(v));
}

// ---------------- dense GEMM: support = features @ W -----------------------
// 128x128 tile, BK=16, 256 threads, 8x8 per thread, fp32 via packed FFMA2.
#define BM 128
#define BN 128
#define BK 16

__global__ __launch_bounds__(256) void gemm_kernel(
    const float* __restrict__ A,   // [N_NODES, IN_F]
    const float* __restrict__ B)   // [IN_F, OUT_F]
{
    __shared__ __align__(16) u64   As[BK][BM];  // A values duplicated into both f32x2 lanes
    __shared__ __align__(16) float Bs[BK][BN];

    const int tid = threadIdx.x;
    const int tx = tid & 15;       // 0..15 -> 8 columns each
    const int ty = tid >> 4;       // 0..15 -> 8 rows each
    const int rowBase = blockIdx.y * BM;
    const int colBase = blockIdx.x * BN;

    u64 acc[8][4];
    #pragma unroll
    for (int i = 0; i < 8; i++)
        #pragma unroll
        for (int j = 0; j < 4; j++) acc[i][j] = 0ull;

    for (int k0 = 0; k0 < IN_F; k0 += BK) {
        // load A tile (128 rows x 16 k), duplicate each value into both lanes
        #pragma unroll
        for (int l = 0; l < 2; l++) {
            int f  = tid + l * 256;
            int r  = f >> 2;
            int kk = (f & 3) << 2;
            float4 v = make_float4(0.f, 0.f, 0.f, 0.f);
            int gr = rowBase + r;
            if (gr < N_NODES)
                v = *(const float4*)(A + (size_t)gr * IN_F + k0 + kk);
            As[kk + 0][r] = dup2(v.x);
            As[kk + 1][r] = dup2(v.y);
            As[kk + 2][r] = dup2(v.z);
            As[kk + 3][r] = dup2(v.w);
        }
        // load B tile (16 k x 128 cols)
        #pragma unroll
        for (int l = 0; l < 2; l++) {
            int f  = tid + l * 256;
            int kk = f >> 5;
            int c  = (f & 31) << 2;
            *(float4*)&Bs[kk][c] =
                *(const float4*)(B + (size_t)(k0 + kk) * OUT_F + colBase + c);
        }
        __syncthreads();

        #pragma unroll
        for (int kk = 0; kk < BK; kk++) {
            u64 a[8], b[4];
            const u64* brow = (const u64*)&Bs[kk][0];
            #pragma unroll
            for (int j = 0; j < 4; j++) b[j] = brow[tx * 4 + j];
            #pragma unroll
            for (int i = 0; i < 8; i++) a[i] = As[kk][ty * 8 + i];
            #pragma unroll
            for (int i = 0; i < 8; i++)
                #pragma unroll
                for (int j = 0; j < 4; j++)
                    acc[i][j] = fma2(a[i], b[j], acc[i][j]);
        }
        __syncthreads();
    }

    // store to g_support
    #pragma unroll
    for (int i = 0; i < 8; i++) {
        int gr = rowBase + ty * 8 + i;
        if (gr >= N_NODES) continue;
        float* out = g_support + (size_t)gr * OUT_F + colBase + tx * 8;
        float a0, a1, b0, b1;
        unpack2(acc[i][0], a0, a1);
        unpack2(acc[i][1], b0, b1);
        *(float4*)out = make_float4(a0, a1, b0, b1);
        unpack2(acc[i][2], a0, a1);
        unpack2(acc[i][3], b0, b1);
        *(float4*)(out + 4) = make_float4(a0, a1, b0, b1);
    }
}

// ---------------- CSR build --------------------------------------------------
__global__ void zero_kernel() {
    int i = blockIdx.x * blockDim.x + threadIdx.x;
    if (i < N_NODES) g_count[i] = 0;
}

__global__ void hist_kernel(const int* __restrict__ row) {
    int e = blockIdx.x * blockDim.x + threadIdx.x;
    if (e < N_EDGES) atomicAdd(&g_count[row[e]], 1);
}

// single-block streaming exclusive scan over g_count -> g_start; re-zeros g_count
__global__ void scan_kernel() {
    __shared__ int warp_sums[32];
    const int t = threadIdx.x;
    const int lane = t & 31, w = t >> 5;
    int carry = 0;
    for (int base = 0; base < N_NODES; base += 1024) {
        int i = base + t;
        int c = (i < N_NODES) ? g_count[i] : 0;
        int incl = c;
        #pragma unroll
        for (int d = 1; d < 32; d <<= 1) {
            int v = __shfl_up_sync(0xffffffffu, incl, d);
            if (lane >= d) incl += v;
        }
        if (lane == 31) warp_sums[w] = incl;
        __syncthreads();
        if (w == 0) {
            int s = warp_sums[lane];
            #pragma unroll
            for (int d = 1; d < 32; d <<= 1) {
                int v = __shfl_up_sync(0xffffffffu, s, d);
                if (lane >= d) s += v;
            }
            warp_sums[lane] = s;
        }
        __syncthreads();
        int woff = (w > 0) ? warp_sums[w - 1] : 0;
        if (i < N_NODES) {
            g_start[i] = carry + woff + incl - c;
            g_count[i] = 0;                       // reset -> cursor for scatter
        }
        carry += warp_sums[31];
        __syncthreads();
    }
    if (t == 0) g_start[N_NODES] = carry;
}

__global__ void scatter_kernel(const int* __restrict__ row,
                               const int* __restrict__ col,
                               const float* __restrict__ val) {
    int e = blockIdx.x * blockDim.x + threadIdx.x;
    if (e < N_EDGES) {
        int r = row[e];
        int p = g_start[r] + atomicAdd(&g_count[r], 1);
        g_col[p] = col[e];
        g_val[p] = val[e];
    }
}

// ---------------- SpMM + ReLU ------------------------------------------------
// one row per (64-thread) group, 4 rows per 256-thread block; float4 per thread
__global__ __launch_bounds__(256) void spmm_kernel(float* __restrict__ out) {
    const int row = blockIdx.x * 4 + threadIdx.y;
    if (row >= N_NODES) return;
    const int lane = threadIdx.x;  // 0..63
    const int s = g_start[row];
    const int e = g_start[row + 1];
    const float4* __restrict__ sup = (const float4*)g_support;

    float4 acc = make_float4(0.f, 0.f, 0.f, 0.f);
    int i = s;
    for (; i + 4 <= e; i += 4) {
        int   c0 = g_col[i],     c1 = g_col[i + 1];
        int   c2 = g_col[i + 2], c3 = g_col[i + 3];
        float v0 = g_val[i],     v1 = g_val[i + 1];
        float v2 = g_val[i + 2], v3 = g_val[i + 3];
        float4 x0 = sup[(size_t)c0 * 64 + lane];
        float4 x1 = sup[(size_t)c1 * 64 + lane];
        float4 x2 = sup[(size_t)c2 * 64 + lane];
        float4 x3 = sup[(size_t)c3 * 64 + lane];
        acc.x += v0 * x0.x; acc.y += v0 * x0.y; acc.z += v0 * x0.z; acc.w += v0 * x0.w;
        acc.x += v1 * x1.x; acc.y += v1 * x1.y; acc.z += v1 * x1.z; acc.w += v1 * x1.w;
        acc.x += v2 * x2.x; acc.y += v2 * x2.y; acc.z += v2 * x2.z; acc.w += v2 * x2.w;
        acc.x += v3 * x3.x; acc.y += v3 * x3.y; acc.z += v3 * x3.z; acc.w += v3 * x3.w;
    }
    for (; i < e; i++) {
        int c = g_col[i];
        float v = g_val[i];
        float4 x = sup[(size_t)c * 64 + lane];
        acc.x += v * x.x; acc.y += v * x.y; acc.z += v * x.z; acc.w += v * x.w;
    }
    acc.x = fmaxf(acc.x, 0.f);
    acc.y = fmaxf(acc.y, 0.f);
    acc.z = fmaxf(acc.z, 0.f);
    acc.w = fmaxf(acc.w, 0.f);
    ((float4*)out)[(size_t)row * 64 + lane] = acc;
}

// ---------------- launch -----------------------------------------------------
extern "C" void kernel_launch(void* const* d_in, const int* in_sizes, int n_in,
                              void* d_out, int out_size) {
    const float* features = (const float*)d_in[0];
    const float* weight   = (const float*)d_in[1];
    const int*   edge_row = (const int*)d_in[2];
    const int*   edge_col = (const int*)d_in[3];
    const float* edge_val = (const float*)d_in[4];
    float* out = (float*)d_out;

    dim3 gemm_grid(OUT_F / BN, (N_NODES + BM - 1) / BM);
    gemm_kernel<<<gemm_grid, 256>>>(features, weight);

    zero_kernel<<<(N_NODES + 255) / 256, 256>>>();
    hist_kernel<<<(N_EDGES + 255) / 256, 256>>>(edge_row);
    scan_kernel<<<1, 1024>>>();
    scatter_kernel<<<(N_EDGES + 255) / 256, 256>>>(edge_row, edge_col, edge_val);

    spmm_kernel<<<(N_NODES + 3) / 4, dim3(64, 4)>>>(out);
    (void)in_sizes; (void)n_in; (void)out_size;
}

// round 2
// speedup vs baseline: 1.1259x; 1.1259x over previous
#include <cuda_runtime.h>
#include <cuda_bf16.h>
#include <cstdint>

#define N_NODES 100000
#define N_EDGES 3200000
#define IN_F 512
#define OUT_F 256

typedef unsigned long long u64;

// ---------------- scratch (device globals; no runtime allocation) ------------
__device__ __align__(16) float g_support[(size_t)N_NODES * OUT_F]; // 102.4 MB
__device__ int   g_count[N_NODES];
__device__ int   g_start[N_NODES + 1];
__device__ int   g_col[N_EDGES];
__device__ float g_val[N_EDGES];
__device__ int   g_bsum[128];
__device__ int   g_boff[128];

#define SCAN_B 1024
#define N_SBLK ((N_NODES + SCAN_B - 1) / SCAN_B)   // 98

// ---------------- packed fp32x2 helpers (Blackwell FFMA2 path) ---------------
__device__ __forceinline__ u64 fma2(u64 a, u64 b, u64 c) {
    u64 d;
    asm("fma.rn.f32x2 %0, %1, %2, %3;" : "=l"(d) : "l"(a), "l"(b), "l"(c));
    return d;
}
__device__ __forceinline__ u64 dup2(float x) {
    u64 r; asm("mov.b64 %0, {%1, %1};" : "=l"(r) : "f"(x)); return r;
}
__device__ __forceinline__ void unpack2(u64 v, float& lo, float& hi) {
    asm("mov.b64 {%0, %1}, %2;" : "=f"(lo), "=f"(hi) : "l"(v));
}

// ---------------- dense GEMM: support = features @ W ------------------------
// 128x128 tile, BK=16, 256 threads, 8x8 per thread, double-buffered smem.
#define BM 128
#define BN 128
#define BK 16
#define NIT (IN_F / BK)

__global__ __launch_bounds__(256, 2) void gemm_kernel(
    const float* __restrict__ A,   // [N_NODES, IN_F]
    const float* __restrict__ B)   // [IN_F, OUT_F]
{
    __shared__ __align__(16) u64   As[2][BK][BM];   // 32 KB
    __shared__ __align__(16) float Bs[2][BK][BN];   // 16 KB

    const int tid = threadIdx.x;
    const int tx = tid & 15;       // 8 cols each
    const int ty = tid >> 4;       // 8 rows each
    const int rowBase = blockIdx.y * BM;
    const int colBase = blockIdx.x * BN;

    // per-thread loader coordinates (fixed)
    const int ar0 = tid >> 2;            // A row (l=0), l=1 adds 64... actually f>>2 spans 0..127
    const int ak0 = (tid & 3) << 2;      // A k within tile
    const int bk0 = tid >> 5;            // B k (l=0), l=1 adds 8
    const int bc0 = (tid & 31) << 2;     // B col

    u64 acc[8][4];
    #pragma unroll
    for (int i = 0; i < 8; i++)
        #pragma unroll
        for (int j = 0; j < 4; j++) acc[i][j] = 0ull;

    float4 aReg[2], bReg[2];

    auto fetch = [&](int k0) {
        #pragma unroll
        for (int l = 0; l < 2; l++) {
            int r = ar0 + l * 64;
            int gr = rowBase + r;
            aReg[l] = make_float4(0.f, 0.f, 0.f, 0.f);
            if (gr < N_NODES)
                aReg[l] = *(const float4*)(A + (size_t)gr * IN_F + k0 + ak0);
            bReg[l] = *(const float4*)(B + (size_t)(k0 + bk0 + l * 8) * OUT_F + colBase + bc0);
        }
    };
    auto stage = [&](int s) {
        #pragma unroll
        for (int l = 0; l < 2; l++) {
            int r = ar0 + l * 64;
            As[s][ak0 + 0][r] = dup2(aReg[l].x);
            As[s][ak0 + 1][r] = dup2(aReg[l].y);
            As[s][ak0 + 2][r] = dup2(aReg[l].z);
            As[s][ak0 + 3][r] = dup2(aReg[l].w);
            *(float4*)&Bs[s][bk0 + l * 8][bc0] = bReg[l];
        }
    };

    fetch(0);
    stage(0);
    __syncthreads();

    for (int it = 0; it < NIT; it++) {
        const int s = it & 1;
        if (it + 1 < NIT) fetch((it + 1) * BK);

        #pragma unroll
        for (int kk = 0; kk < BK; kk++) {
            u64 a[8], b[4];
            const u64* brow = (const u64*)&Bs[s][kk][0];
            #pragma unroll
            for (int j = 0; j < 4; j++) b[j] = brow[tx * 4 + j];
            #pragma unroll
            for (int i = 0; i < 8; i++) a[i] = As[s][kk][ty * 8 + i];
            #pragma unroll
            for (int i = 0; i < 8; i++)
                #pragma unroll
                for (int j = 0; j < 4; j++)
                    acc[i][j] = fma2(a[i], b[j], acc[i][j]);
        }

        if (it + 1 < NIT) {
            stage(s ^ 1);
            __syncthreads();
        }
    }

    #pragma unroll
    for (int i = 0; i < 8; i++) {
        int gr = rowBase + ty * 8 + i;
        if (gr >= N_NODES) continue;
        float* out = g_support + (size_t)gr * OUT_F + colBase + tx * 8;
        float a0, a1, b0, b1;
        unpack2(acc[i][0], a0, a1);
        unpack2(acc[i][1], b0, b1);
        *(float4*)out = make_float4(a0, a1, b0, b1);
        unpack2(acc[i][2], a0, a1);
        unpack2(acc[i][3], b0, b1);
        *(float4*)(out + 4) = make_float4(a0, a1, b0, b1);
    }
}

// ---------------- CSR build --------------------------------------------------
__global__ void zero_kernel() {
    int i = blockIdx.x * blockDim.x + threadIdx.x;
    if (i < N_NODES) g_count[i] = 0;
}

__global__ void hist_kernel(const int* __restrict__ row) {
    int e = blockIdx.x * blockDim.x + threadIdx.x;
    if (e < N_EDGES) atomicAdd(&g_count[row[e]], 1);
}

// local exclusive scan per 1024-block; block total -> g_bsum
__global__ __launch_bounds__(1024) void scan1_kernel() {
    __shared__ int ws[32];
    const int t = threadIdx.x, lane = t & 31, w = t >> 5;
    const int i = blockIdx.x * SCAN_B + t;
    int c = (i < N_NODES) ? g_count[i] : 0;
    int incl = c;
    #pragma unroll
    for (int d = 1; d < 32; d <<= 1) {
        int v = __shfl_up_sync(0xffffffffu, incl, d);
        if (lane >= d) incl += v;
    }
    if (lane == 31) ws[w] = incl;
    __syncthreads();
    if (w == 0) {
        int s = ws[lane];
        #pragma unroll
        for (int d = 1; d < 32; d <<= 1) {
            int v = __shfl_up_sync(0xffffffffu, s, d);
            if (lane >= d) s += v;
        }
        ws[lane] = s;
    }
    __syncthreads();
    int off = (w > 0) ? ws[w - 1] : 0;
    if (i < N_NODES) g_start[i] = off + incl - c;
    if (t == SCAN_B - 1) g_bsum[blockIdx.x] = ws[31];
}

// scan the 98 block sums (1 block, 128 threads)
__global__ void scan2_kernel() {
    __shared__ int ws[4];
    const int t = threadIdx.x, lane = t & 31, w = t >> 5;
    int c = (t < N_SBLK) ? g_bsum[t] : 0;
    int incl = c;
    #pragma unroll
    for (int d = 1; d < 32; d <<= 1) {
        int v = __shfl_up_sync(0xffffffffu, incl, d);
        if (lane >= d) incl += v;
    }
    if (lane == 31) ws[w] = incl;
    __syncthreads();
    int woff = 0;
    #pragma unroll
    for (int j = 0; j < 4; j++) if (j < w) woff += ws[j];
    if (t < N_SBLK) g_boff[t] = woff + incl - c;
    if (t == 0) g_start[N_NODES] = ws[0] + ws[1] + ws[2] + ws[3];
}

// add block offsets; reset counters for scatter cursors
__global__ __launch_bounds__(1024) void scan3_kernel() {
    const int i = blockIdx.x * SCAN_B + threadIdx.x;
    if (i < N_NODES) {
        g_start[i] += g_boff[blockIdx.x];
        g_count[i] = 0;
    }
}

__global__ void scatter_kernel(const int* __restrict__ row,
                               const int* __restrict__ col,
                               const float* __restrict__ val) {
    int e = blockIdx.x * blockDim.x + threadIdx.x;
    if (e < N_EDGES) {
        int r = row[e];
        int p = g_start[r] + atomicAdd(&g_count[r], 1);
        g_col[p] = col[e];
        g_val[p] = val[e];
    }
}

// ---------------- SpMM + ReLU (column-split: 128 cols per pass) --------------
// one row per 32-thread warp, 8 rows per 256-thread block; float4 per thread
__global__ __launch_bounds__(256) void spmm_kernel(float* __restrict__ out,
                                                   int colOff /* in float4 units */) {
    const int row = blockIdx.x * 8 + threadIdx.y;
    if (row >= N_NODES) return;
    const int lane = threadIdx.x;                 // 0..31
    const int s = g_start[row];
    const int e = g_start[row + 1];
    const float4* __restrict__ sup = (const float4*)g_support;
    const size_t lo = (size_t)colOff + lane;

    float4 acc = make_float4(0.f, 0.f, 0.f, 0.f);
    int i = s;
    for (; i + 4 <= e; i += 4) {
        int   c0 = g_col[i],     c1 = g_col[i + 1];
        int   c2 = g_col[i + 2], c3 = g_col[i + 3];
        float v0 = g_val[i],     v1 = g_val[i + 1];
        float v2 = g_val[i + 2], v3 = g_val[i + 3];
        float4 x0 = __ldg(sup + (size_t)c0 * 64 + lo);
        float4 x1 = __ldg(sup + (size_t)c1 * 64 + lo);
        float4 x2 = __ldg(sup + (size_t)c2 * 64 + lo);
        float4 x3 = __ldg(sup + (size_t)c3 * 64 + lo);
        acc.x += v0 * x0.x; acc.y += v0 * x0.y; acc.z += v0 * x0.z; acc.w += v0 * x0.w;
        acc.x += v1 * x1.x; acc.y += v1 * x1.y; acc.z += v1 * x1.z; acc.w += v1 * x1.w;
        acc.x += v2 * x2.x; acc.y += v2 * x2.y; acc.z += v2 * x2.z; acc.w += v2 * x2.w;
        acc.x += v3 * x3.x; acc.y += v3 * x3.y; acc.z += v3 * x3.z; acc.w += v3 * x3.w;
    }
    for (; i < e; i++) {
        int c = g_col[i];
        float v = g_val[i];
        float4 x = __ldg(sup + (size_t)c * 64 + lo);
        acc.x += v * x.x; acc.y += v * x.y; acc.z += v * x.z; acc.w += v * x.w;
    }
    acc.x = fmaxf(acc.x, 0.f);
    acc.y = fmaxf(acc.y, 0.f);
    acc.z = fmaxf(acc.z, 0.f);
    acc.w = fmaxf(acc.w, 0.f);
    ((float4*)out)[(size_t)row * 64 + lo] = acc;
}

// ---------------- launch -----------------------------------------------------
extern "C" void kernel_launch(void* const* d_in, const int* in_sizes, int n_in,
                              void* d_out, int out_size) {
    const float* features = (const float*)d_in[0];
    const float* weight   = (const float*)d_in[1];
    const int*   edge_row = (const int*)d_in[2];
    const int*   edge_col = (const int*)d_in[3];
    const float* edge_val = (const float*)d_in[4];
    float* out = (float*)d_out;

    dim3 gemm_grid(OUT_F / BN, (N_NODES + BM - 1) / BM);
    gemm_kernel<<<gemm_grid, 256>>>(features, weight);

    zero_kernel<<<(N_NODES + 255) / 256, 256>>>();
    hist_kernel<<<(N_EDGES + 255) / 256, 256>>>(edge_row);
    scan1_kernel<<<N_SBLK, SCAN_B>>>();
    scan2_kernel<<<1, 128>>>();
    scan3_kernel<<<N_SBLK, SCAN_B>>>();
    scatter_kernel<<<(N_EDGES + 255) / 256, 256>>>(edge_row, edge_col, edge_val);

    dim3 spmm_block(32, 8);
    int spmm_grid = (N_NODES + 7) / 8;
    spmm_kernel<<<spmm_grid, spmm_block>>>(out, 0);
    spmm_kernel<<<spmm_grid, spmm_block>>>(out, 32);

    (void)in_sizes; (void)n_in; (void)out_size;
}

// round 5
// speedup vs baseline: 2.1793x; 1.9356x over previous
#include <cuda_runtime.h>
#include <cuda_bf16.h>
#include <cstdint>

#define N_NODES 100000
#define N_EDGES 3200000
#define IN_F 512
#define OUT_F 256

typedef unsigned long long u64;

// ---------------- scratch (device globals; no runtime allocation) ------------
__device__ __align__(16) float g_support[(size_t)N_NODES * OUT_F]; // 102.4 MB
__device__ int   g_count[N_NODES];
__device__ int   g_start[N_NODES + 1];
__device__ int   g_col[N_EDGES];
__device__ float g_val[N_EDGES];
__device__ int   g_bsum[128];
__device__ int   g_boff[128];
// weight transposed+split to bf16 hi/lo, [N=256][K=512] K-major
__device__ __align__(16) __nv_bfloat16 g_Bt_hi[OUT_F * IN_F];
__device__ __align__(16) __nv_bfloat16 g_Bt_lo[OUT_F * IN_F];

#define SCAN_B 1024
#define N_SBLK ((N_NODES + SCAN_B - 1) / SCAN_B)   // 98

// ---------------- base-ISA tensor-core helpers (sm_80+ PTX only) -------------
__device__ __forceinline__ uint32_t smem_to_u32(const void* p) {
    uint32_t a;
    asm("{ .reg .u64 t; cvta.to.shared.u64 t, %1; cvt.u32.u64 %0, t; }"
        : "=r"(a) : "l"(p));
    return a;
}
#define LDSM_X4(r0, r1, r2, r3, addr) \
    asm volatile("ldmatrix.sync.aligned.m8n8.x4.shared.b16 {%0,%1,%2,%3}, [%4];" \
        : "=r"(r0), "=r"(r1), "=r"(r2), "=r"(r3) : "r"(addr))
#define MMA_BF16(d0, d1, d2, d3, a0, a1, a2, a3, b0, b1) \
    asm volatile("mma.sync.aligned.m16n8k16.row.col.f32.bf16.bf16.f32 " \
        "{%0,%1,%2,%3}, {%4,%5,%6,%7}, {%8,%9}, {%0,%1,%2,%3};" \
        : "+f"(d0), "+f"(d1), "+f"(d2), "+f"(d3) \
        : "r"(a0), "r"(a1), "r"(a2), "r"(a3), "r"(b0), "r"(b1))

// --------- weight transpose + bf16 hi/lo split (also zeroes g_count) ---------
__global__ void bconv_kernel(const float* __restrict__ W) {
    int i = blockIdx.x * blockDim.x + threadIdx.x;
    if (i < N_NODES) g_count[i] = 0;
    if (i < IN_F * OUT_F) {
        int k = i >> 8, n = i & 255;          // W[k][n], row-major [512,256]
        float v = W[i];
        __nv_bfloat16 h = __float2bfloat16(v);
        float lo = v - __bfloat162float(h);
        g_Bt_hi[n * IN_F + k] = h;
        g_Bt_lo[n * IN_F + k] = __float2bfloat16(lo);
    }
}

// ---------------- mma.sync GEMM: support = features @ W ----------------------
// CTA tile 128x128, KC=32, double-buffered smem; 8 warps, each 64(M)x32(N).
// 3-term bf16 split: Ahi*Bhi + Ahi*Blo + Alo*Bhi, fp32 accumulate.
#define KC 32
#define NKC (IN_F / KC)            // 16
#define LDS_T 40                   // row stride in bf16 elems (32 data + 8 pad = 80B)
#define TILE_B (128 * LDS_T * 2)   // 10240 bytes per [128][40] bf16 array
// per-stage: Ahi, Alo, Bhi, Blo
#define SM_STAGE (4 * TILE_B)      // 40960
#define SM_TOTAL (2 * SM_STAGE)    // 81920
#define OFF_AHI(s) ((s) * SM_STAGE)
#define OFF_ALO(s) (OFF_AHI(s) + TILE_B)
#define OFF_BHI(s) (OFF_AHI(s) + 2 * TILE_B)
#define OFF_BLO(s) (OFF_AHI(s) + 3 * TILE_B)

__global__ __launch_bounds__(256, 1) void gemm_mma_kernel(
    const float* __restrict__ A)           // features [N_NODES, IN_F]
{
    extern __shared__ char smem[];
    const uint32_t sb = smem_to_u32(smem);
    const int tid  = threadIdx.x;
    const int wid  = tid >> 5;
    const int lane = tid & 31;
    const int rowBase = blockIdx.y * 128;
    const int colBase = blockIdx.x * 128;
    const int warpM = (wid & 1) * 64;      // 2 M-groups of 64
    const int warpN = (wid >> 1) * 32;     // 4 N-groups of 32

    // accumulators: 4 m-tiles x 4 n-tiles x 4 floats
    float acc[4][4][4];
    #pragma unroll
    for (int i = 0; i < 4; i++)
        #pragma unroll
        for (int j = 0; j < 4; j++)
            #pragma unroll
            for (int q = 0; q < 4; q++) acc[i][j][q] = 0.f;

    // fetch registers
    float4 aF[4];
    uint4  bFh[2], bFl[2];

    // A fetch coords: 1024 float4 per chunk -> 4/thread. row=idx>>3, kq=idx&7
    // B fetch coords: 512 uint4 per array -> 2/thread. n=idx>>2, kq=idx&3
    auto fetchA = [&](int k0) {
        #pragma unroll
        for (int j = 0; j < 4; j++) {
            int idx = tid + j * 256;
            int row = idx >> 3, kq = idx & 7;
            int gr = rowBase + row;
            aF[j] = make_float4(0.f, 0.f, 0.f, 0.f);
            if (gr < N_NODES)
                aF[j] = __ldg((const float4*)(A + (size_t)gr * IN_F + k0 + kq * 4));
        }
        #pragma unroll
        for (int j = 0; j < 2; j++) {
            int idx = tid + j * 256;
            int n = idx >> 2, kq = idx & 3;
            bFh[j] = __ldg((const uint4*)(g_Bt_hi + (size_t)(colBase + n) * IN_F + k0 + kq * 8));
            bFl[j] = __ldg((const uint4*)(g_Bt_lo + (size_t)(colBase + n) * IN_F + k0 + kq * 8));
        }
    };
    auto stage = [&](int s) {
        char* ahi = smem + OFF_AHI(s);
        char* alo = smem + OFF_ALO(s);
        char* bhi = smem + OFF_BHI(s);
        char* blo = smem + OFF_BLO(s);
        #pragma unroll
        for (int j = 0; j < 4; j++) {
            int idx = tid + j * 256;
            int row = idx >> 3, kq = idx & 7;
            float4 v = aF[j];
            __nv_bfloat162 h01 = __floats2bfloat162_rn(v.x, v.y);
            __nv_bfloat162 h23 = __floats2bfloat162_rn(v.z, v.w);
            float2 f01 = __bfloat1622float2(h01);
            float2 f23 = __bfloat1622float2(h23);
            __nv_bfloat162 l01 = __floats2bfloat162_rn(v.x - f01.x, v.y - f01.y);
            __nv_bfloat162 l23 = __floats2bfloat162_rn(v.z - f23.x, v.w - f23.y);
            uint32_t off = (uint32_t)(row * 80 + kq * 8);
            *(uint2*)(ahi + off) = make_uint2(*(uint32_t*)&h01, *(uint32_t*)&h23);
            *(uint2*)(alo + off) = make_uint2(*(uint32_t*)&l01, *(uint32_t*)&l23);
        }
        #pragma unroll
        for (int j = 0; j < 2; j++) {
            int idx = tid + j * 256;
            int n = idx >> 2, kq = idx & 3;
            uint32_t off = (uint32_t)(n * 80 + kq * 16);
            *(uint4*)(bhi + off) = bFh[j];
            *(uint4*)(blo + off) = bFl[j];
        }
    };

    fetchA(0);
    stage(0);

    for (int c = 0; c < NKC; c++) {
        const int s = c & 1;
        if (c + 1 < NKC) fetchA((c + 1) * KC);
        __syncthreads();

        // compute on buffer s
        const uint32_t ahiB = sb + OFF_AHI(s);
        const uint32_t aloB = sb + OFF_ALO(s);
        const uint32_t bhiB = sb + OFF_BHI(s);
        const uint32_t bloB = sb + OFF_BLO(s);
        // ldmatrix lane addressing
        const uint32_t aRow = (uint32_t)(warpM + (lane & 15));
        const uint32_t aKx  = (uint32_t)((lane >> 4) * 16);          // bytes
        const uint32_t bNr  = (uint32_t)(warpN + (lane & 7) + ((lane >> 4) << 3));
        const uint32_t bKx  = (uint32_t)(((lane >> 3) & 1) * 16);    // bytes

        #pragma unroll
        for (int ks = 0; ks < 2; ks++) {
            const uint32_t kByte = (uint32_t)(ks * 32);
            uint32_t Ah[4][4], Al[4][4], Bh[4][2], Bl[4][2];
            #pragma unroll
            for (int mt = 0; mt < 4; mt++) {
                uint32_t ao = (aRow + mt * 16) * 80 + kByte + aKx;
                LDSM_X4(Ah[mt][0], Ah[mt][1], Ah[mt][2], Ah[mt][3], ahiB + ao);
                LDSM_X4(Al[mt][0], Al[mt][1], Al[mt][2], Al[mt][3], aloB + ao);
            }
            #pragma unroll
            for (int np = 0; np < 2; np++) {   // pair of n8 tiles per ldmatrix.x4
                uint32_t bo = (bNr + np * 16) * 80 + kByte + bKx;
                LDSM_X4(Bh[np * 2][0], Bh[np * 2][1], Bh[np * 2 + 1][0], Bh[np * 2 + 1][1], bhiB + bo);
                LDSM_X4(Bl[np * 2][0], Bl[np * 2][1], Bl[np * 2 + 1][0], Bl[np * 2 + 1][1], bloB + bo);
            }
            #pragma unroll
            for (int mt = 0; mt < 4; mt++)
                #pragma unroll
                for (int nt = 0; nt < 4; nt++) {
                    MMA_BF16(acc[mt][nt][0], acc[mt][nt][1], acc[mt][nt][2], acc[mt][nt][3],
                             Ah[mt][0], Ah[mt][1], Ah[mt][2], Ah[mt][3],
                             Bh[nt][0], Bh[nt][1]);
                    MMA_BF16(acc[mt][nt][0], acc[mt][nt][1], acc[mt][nt][2], acc[mt][nt][3],
                             Ah[mt][0], Ah[mt][1], Ah[mt][2], Ah[mt][3],
                             Bl[nt][0], Bl[nt][1]);
                    MMA_BF16(acc[mt][nt][0], acc[mt][nt][1], acc[mt][nt][2], acc[mt][nt][3],
                             Al[mt][0], Al[mt][1], Al[mt][2], Al[mt][3],
                             Bh[nt][0], Bh[nt][1]);
                }
        }

        if (c + 1 < NKC) stage((c + 1) & 1);
    }

    // epilogue: fragment layout -> g_support (fp32)
    const int rq = lane >> 2;           // 0..7
    const int cq = (lane & 3) * 2;      // 0,2,4,6
    #pragma unroll
    for (int mt = 0; mt < 4; mt++) {
        int r0 = rowBase + warpM + mt * 16 + rq;
        #pragma unroll
        for (int nt = 0; nt < 4; nt++) {
            int cc = colBase + warpN + nt * 8 + cq;
            if (r0 < N_NODES)
                *(float2*)(g_support + (size_t)r0 * OUT_F + cc) =
                    make_float2(acc[mt][nt][0], acc[mt][nt][1]);
            if (r0 + 8 < N_NODES)
                *(float2*)(g_support + (size_t)(r0 + 8) * OUT_F + cc) =
                    make_float2(acc[mt][nt][2], acc[mt][nt][3]);
        }
    }
}

// ---------------- CSR build --------------------------------------------------
__global__ void hist_kernel(const int* __restrict__ row) {
    int e = blockIdx.x * blockDim.x + threadIdx.x;
    if (e < N_EDGES) atomicAdd(&g_count[row[e]], 1);
}

__global__ __launch_bounds__(1024) void scan1_kernel() {
    __shared__ int ws[32];
    const int t = threadIdx.x, lane = t & 31, w = t >> 5;
    const int i = blockIdx.x * SCAN_B + t;
    int c = (i < N_NODES) ? g_count[i] : 0;
    int incl = c;
    #pragma unroll
    for (int d = 1; d < 32; d <<= 1) {
        int v = __shfl_up_sync(0xffffffffu, incl, d);
        if (lane >= d) incl += v;
    }
    if (lane == 31) ws[w] = incl;
    __syncthreads();
    if (w == 0) {
        int s = ws[lane];
        #pragma unroll
        for (int d = 1; d < 32; d <<= 1) {
            int v = __shfl_up_sync(0xffffffffu, s, d);
            if (lane >= d) s += v;
        }
        ws[lane] = s;
    }
    __syncthreads();
    int off = (w > 0) ? ws[w - 1] : 0;
    if (i < N_NODES) g_start[i] = off + incl - c;
    if (t == SCAN_B - 1) g_bsum[blockIdx.x] = ws[31];
}

__global__ void scan2_kernel() {
    __shared__ int ws[4];
    const int t = threadIdx.x, lane = t & 31, w = t >> 5;
    int c = (t < N_SBLK) ? g_bsum[t] : 0;
    int incl = c;
    #pragma unroll
    for (int d = 1; d < 32; d <<= 1) {
        int v = __shfl_up_sync(0xffffffffu, incl, d);
        if (lane >= d) incl += v;
    }
    if (lane == 31) ws[w] = incl;
    __syncthreads();
    int woff = 0;
    #pragma unroll
    for (int j = 0; j < 4; j++) if (j < w) woff += ws[j];
    if (t < N_SBLK) g_boff[t] = woff + incl - c;
    if (t == 0) g_start[N_NODES] = ws[0] + ws[1] + ws[2] + ws[3];
}

__global__ __launch_bounds__(1024) void scan3_kernel() {
    const int i = blockIdx.x * SCAN_B + threadIdx.x;
    if (i < N_NODES) {
        g_start[i] += g_boff[blockIdx.x];
        g_count[i] = 0;
    }
}

__global__ void scatter_kernel(const int* __restrict__ row,
                               const int* __restrict__ col,
                               const float* __restrict__ val) {
    int e = blockIdx.x * blockDim.x + threadIdx.x;
    if (e < N_EDGES) {
        int r = row[e];
        int p = g_start[r] + atomicAdd(&g_count[r], 1);
        g_col[p] = col[e];
        g_val[p] = val[e];
    }
}

// ---------------- SpMM + ReLU (column-split: 128 cols per pass) --------------
__global__ __launch_bounds__(256) void spmm_kernel(float* __restrict__ out,
                                                   int colOff /* float4 units */) {
    const int row = blockIdx.x * 8 + threadIdx.y;
    if (row >= N_NODES) return;
    const int lane = threadIdx.x;                 // 0..31
    const int s = g_start[row];
    const int e = g_start[row + 1];
    const float4* __restrict__ sup = (const float4*)g_support;
    const size_t lo = (size_t)colOff + lane;

    float4 acc = make_float4(0.f, 0.f, 0.f, 0.f);
    int i = s;
    for (; i + 4 <= e; i += 4) {
        int   c0 = g_col[i],     c1 = g_col[i + 1];
        int   c2 = g_col[i + 2], c3 = g_col[i + 3];
        float v0 = g_val[i],     v1 = g_val[i + 1];
        float v2 = g_val[i + 2], v3 = g_val[i + 3];
        float4 x0 = __ldg(sup + (size_t)c0 * 64 + lo);
        float4 x1 = __ldg(sup + (size_t)c1 * 64 + lo);
        float4 x2 = __ldg(sup + (size_t)c2 * 64 + lo);
        float4 x3 = __ldg(sup + (size_t)c3 * 64 + lo);
        acc.x += v0 * x0.x; acc.y += v0 * x0.y; acc.z += v0 * x0.z; acc.w += v0 * x0.w;
        acc.x += v1 * x1.x; acc.y += v1 * x1.y; acc.z += v1 * x1.z; acc.w += v1 * x1.w;
        acc.x += v2 * x2.x; acc.y += v2 * x2.y; acc.z += v2 * x2.z; acc.w += v2 * x2.w;
        acc.x += v3 * x3.x; acc.y += v3 * x3.y; acc.z += v3 * x3.z; acc.w += v3 * x3.w;
    }
    for (; i < e; i++) {
        int c = g_col[i];
        float v = g_val[i];
        float4 x = __ldg(sup + (size_t)c * 64 + lo);
        acc.x += v * x.x; acc.y += v * x.y; acc.z += v * x.z; acc.w += v * x.w;
    }
    acc.x = fmaxf(acc.x, 0.f);
    acc.y = fmaxf(acc.y, 0.f);
    acc.z = fmaxf(acc.z, 0.f);
    acc.w = fmaxf(acc.w, 0.f);
    ((float4*)out)[(size_t)row * 64 + lo] = acc;
}

// ---------------- launch -----------------------------------------------------
extern "C" void kernel_launch(void* const* d_in, const int* in_sizes, int n_in,
                              void* d_out, int out_size) {
    const float* features = (const float*)d_in[0];
    const float* weight   = (const float*)d_in[1];
    const int*   edge_row = (const int*)d_in[2];
    const int*   edge_col = (const int*)d_in[3];
    const float* edge_val = (const float*)d_in[4];
    float* out = (float*)d_out;

    cudaFuncSetAttribute(gemm_mma_kernel,
                         cudaFuncAttributeMaxDynamicSharedMemorySize, SM_TOTAL);

    bconv_kernel<<<(IN_F * OUT_F + 255) / 256, 256>>>(weight);

    dim3 gemm_grid(OUT_F / 128, (N_NODES + 127) / 128);
    gemm_mma_kernel<<<gemm_grid, 256, SM_TOTAL>>>(features);

    hist_kernel<<<(N_EDGES + 255) / 256, 256>>>(edge_row);
    scan1_kernel<<<N_SBLK, SCAN_B>>>();
    scan2_kernel<<<1, 128>>>();
    scan3_kernel<<<N_SBLK, SCAN_B>>>();
    scatter_kernel<<<(N_EDGES + 255) / 256, 256>>>(edge_row, edge_col, edge_val);

    dim3 spmm_block(32, 8);
    int spmm_grid = (N_NODES + 7) / 8;
    spmm_kernel<<<spmm_grid, spmm_block>>>(out, 0);
    spmm_kernel<<<spmm_grid, spmm_block>>>(out, 32);

    (void)in_sizes; (void)n_in; (void)out_size;
}

// round 6
// speedup vs baseline: 2.4945x; 1.1446x over previous
#include <cuda_runtime.h>
#include <cuda_bf16.h>
#include <cuda_fp16.h>
#include <cstdint>

#define N_NODES 100000
#define N_EDGES 3200000
#define IN_F 512
#define OUT_F 256

typedef unsigned long long u64;

// ---------------- scratch (device globals; no runtime allocation) ------------
__device__ __align__(16) __half g_support_h[(size_t)N_NODES * OUT_F]; // 51.2 MB
__device__ int   g_count[N_NODES];
__device__ int   g_start[N_NODES + 1];
__device__ int   g_col[N_EDGES];
__device__ float g_val[N_EDGES];
__device__ int   g_bsum[128];
__device__ int   g_boff[128];
// weight transposed+split to bf16 hi/lo, [N=256][K=512] K-major
__device__ __align__(16) __nv_bfloat16 g_Bt_hi[OUT_F * IN_F];
__device__ __align__(16) __nv_bfloat16 g_Bt_lo[OUT_F * IN_F];

#define SCAN_B 1024
#define N_SBLK ((N_NODES + SCAN_B - 1) / SCAN_B)   // 98

// ---------------- base-ISA tensor-core helpers (sm_80+ PTX only) -------------
__device__ __forceinline__ uint32_t smem_to_u32(const void* p) {
    uint32_t a;
    asm("{ .reg .u64 t; cvta.to.shared.u64 t, %1; cvt.u32.u64 %0, t; }"
        : "=r"(a) : "l"(p));
    return a;
}
#define LDSM_X4(r0, r1, r2, r3, addr) \
    asm volatile("ldmatrix.sync.aligned.m8n8.x4.shared.b16 {%0,%1,%2,%3}, [%4];" \
        : "=r"(r0), "=r"(r1), "=r"(r2), "=r"(r3) : "r"(addr))
#define MMA_BF16(d0, d1, d2, d3, a0, a1, a2, a3, b0, b1) \
    asm volatile("mma.sync.aligned.m16n8k16.row.col.f32.bf16.bf16.f32 " \
        "{%0,%1,%2,%3}, {%4,%5,%6,%7}, {%8,%9}, {%0,%1,%2,%3};" \
        : "+f"(d0), "+f"(d1), "+f"(d2), "+f"(d3) \
        : "r"(a0), "r"(a1), "r"(a2), "r"(a3), "r"(b0), "r"(b1))

// --------- weight transpose + bf16 hi/lo split (also zeroes g_count) ---------
__global__ void bconv_kernel(const float* __restrict__ W) {
    int i = blockIdx.x * blockDim.x + threadIdx.x;
    if (i < N_NODES) g_count[i] = 0;
    if (i < IN_F * OUT_F) {
        int k = i >> 8, n = i & 255;          // W[k][n], row-major [512,256]
        float v = W[i];
        __nv_bfloat16 h = __float2bfloat16(v);
        float lo = v - __bfloat162float(h);
        g_Bt_hi[n * IN_F + k] = h;
        g_Bt_lo[n * IN_F + k] = __float2bfloat16(lo);
    }
}

// ---------------- mma.sync GEMM: support = features @ W ----------------------
// CTA tile 128x128, KC=32, double-buffered smem; 8 warps, each 64(M)x32(N).
// 3-term bf16 split: Ahi*Bhi + Ahi*Blo + Alo*Bhi, fp32 accumulate, fp16 out.
#define KC 32
#define NKC (IN_F / KC)            // 16
#define LDS_T 40                   // row stride in bf16 elems (32 data + 8 pad = 80B)
#define TILE_B (128 * LDS_T * 2)   // 10240 bytes per [128][40] bf16 array
#define SM_STAGE (4 * TILE_B)      // 40960
#define SM_TOTAL (2 * SM_STAGE)    // 81920
#define OFF_AHI(s) ((s) * SM_STAGE)
#define OFF_ALO(s) (OFF_AHI(s) + TILE_B)
#define OFF_BHI(s) (OFF_AHI(s) + 2 * TILE_B)
#define OFF_BLO(s) (OFF_AHI(s) + 3 * TILE_B)

__global__ __launch_bounds__(256, 1) void gemm_mma_kernel(
    const float* __restrict__ A)           // features [N_NODES, IN_F]
{
    extern __shared__ char smem[];
    const uint32_t sb = smem_to_u32(smem);
    const int tid  = threadIdx.x;
    const int wid  = tid >> 5;
    const int lane = tid & 31;
    const int rowBase = blockIdx.y * 128;
    const int colBase = blockIdx.x * 128;
    const int warpM = (wid & 1) * 64;      // 2 M-groups of 64
    const int warpN = (wid >> 1) * 32;     // 4 N-groups of 32

    float acc[4][4][4];
    #pragma unroll
    for (int i = 0; i < 4; i++)
        #pragma unroll
        for (int j = 0; j < 4; j++)
            #pragma unroll
            for (int q = 0; q < 4; q++) acc[i][j][q] = 0.f;

    float4 aF[4];
    uint4  bFh[2], bFl[2];

    auto fetchA = [&](int k0) {
        #pragma unroll
        for (int j = 0; j < 4; j++) {
            int idx = tid + j * 256;
            int row = idx >> 3, kq = idx & 7;
            int gr = rowBase + row;
            aF[j] = make_float4(0.f, 0.f, 0.f, 0.f);
            if (gr < N_NODES)
                aF[j] = __ldg((const float4*)(A + (size_t)gr * IN_F + k0 + kq * 4));
        }
        #pragma unroll
        for (int j = 0; j < 2; j++) {
            int idx = tid + j * 256;
            int n = idx >> 2, kq = idx & 3;
            bFh[j] = __ldg((const uint4*)(g_Bt_hi + (size_t)(colBase + n) * IN_F + k0 + kq * 8));
            bFl[j] = __ldg((const uint4*)(g_Bt_lo + (size_t)(colBase + n) * IN_F + k0 + kq * 8));
        }
    };
    auto stage = [&](int s) {
        char* ahi = smem + OFF_AHI(s);
        char* alo = smem + OFF_ALO(s);
        char* bhi = smem + OFF_BHI(s);
        char* blo = smem + OFF_BLO(s);
        #pragma unroll
        for (int j = 0; j < 4; j++) {
            int idx = tid + j * 256;
            int row = idx >> 3, kq = idx & 7;
            float4 v = aF[j];
            __nv_bfloat162 h01 = __floats2bfloat162_rn(v.x, v.y);
            __nv_bfloat162 h23 = __floats2bfloat162_rn(v.z, v.w);
            float2 f01 = __bfloat1622float2(h01);
            float2 f23 = __bfloat1622float2(h23);
            __nv_bfloat162 l01 = __floats2bfloat162_rn(v.x - f01.x, v.y - f01.y);
            __nv_bfloat162 l23 = __floats2bfloat162_rn(v.z - f23.x, v.w - f23.y);
            uint32_t off = (uint32_t)(row * 80 + kq * 8);
            *(uint2*)(ahi + off) = make_uint2(*(uint32_t*)&h01, *(uint32_t*)&h23);
            *(uint2*)(alo + off) = make_uint2(*(uint32_t*)&l01, *(uint32_t*)&l23);
        }
        #pragma unroll
        for (int j = 0; j < 2; j++) {
            int idx = tid + j * 256;
            int n = idx >> 2, kq = idx & 3;
            uint32_t off = (uint32_t)(n * 80 + kq * 16);
            *(uint4*)(bhi + off) = bFh[j];
            *(uint4*)(blo + off) = bFl[j];
        }
    };

    fetchA(0);
    stage(0);

    for (int c = 0; c < NKC; c++) {
        const int s = c & 1;
        if (c + 1 < NKC) fetchA((c + 1) * KC);
        __syncthreads();

        const uint32_t ahiB = sb + OFF_AHI(s);
        const uint32_t aloB = sb + OFF_ALO(s);
        const uint32_t bhiB = sb + OFF_BHI(s);
        const uint32_t bloB = sb + OFF_BLO(s);
        const uint32_t aRow = (uint32_t)(warpM + (lane & 15));
        const uint32_t aKx  = (uint32_t)((lane >> 4) * 16);          // bytes
        const uint32_t bNr  = (uint32_t)(warpN + (lane & 7) + ((lane >> 4) << 3));
        const uint32_t bKx  = (uint32_t)(((lane >> 3) & 1) * 16);    // bytes

        #pragma unroll
        for (int ks = 0; ks < 2; ks++) {
            const uint32_t kByte = (uint32_t)(ks * 32);
            uint32_t Ah[4][4], Al[4][4], Bh[4][2], Bl[4][2];
            #pragma unroll
            for (int mt = 0; mt < 4; mt++) {
                uint32_t ao = (aRow + mt * 16) * 80 + kByte + aKx;
                LDSM_X4(Ah[mt][0], Ah[mt][1], Ah[mt][2], Ah[mt][3], ahiB + ao);
                LDSM_X4(Al[mt][0], Al[mt][1], Al[mt][2], Al[mt][3], aloB + ao);
            }
            #pragma unroll
            for (int np = 0; np < 2; np++) {
                uint32_t bo = (bNr + np * 16) * 80 + kByte + bKx;
                LDSM_X4(Bh[np * 2][0], Bh[np * 2][1], Bh[np * 2 + 1][0], Bh[np * 2 + 1][1], bhiB + bo);
                LDSM_X4(Bl[np * 2][0], Bl[np * 2][1], Bl[np * 2 + 1][0], Bl[np * 2 + 1][1], bloB + bo);
            }
            #pragma unroll
            for (int mt = 0; mt < 4; mt++)
                #pragma unroll
                for (int nt = 0; nt < 4; nt++) {
                    MMA_BF16(acc[mt][nt][0], acc[mt][nt][1], acc[mt][nt][2], acc[mt][nt][3],
                             Ah[mt][0], Ah[mt][1], Ah[mt][2], Ah[mt][3],
                             Bh[nt][0], Bh[nt][1]);
                    MMA_BF16(acc[mt][nt][0], acc[mt][nt][1], acc[mt][nt][2], acc[mt][nt][3],
                             Ah[mt][0], Ah[mt][1], Ah[mt][2], Ah[mt][3],
                             Bl[nt][0], Bl[nt][1]);
                    MMA_BF16(acc[mt][nt][0], acc[mt][nt][1], acc[mt][nt][2], acc[mt][nt][3],
                             Al[mt][0], Al[mt][1], Al[mt][2], Al[mt][3],
                             Bh[nt][0], Bh[nt][1]);
                }
        }

        if (c + 1 < NKC) stage((c + 1) & 1);
    }

    // epilogue: fragment layout -> g_support_h (fp16)
    const int rq = lane >> 2;           // 0..7
    const int cq = (lane & 3) * 2;      // 0,2,4,6
    #pragma unroll
    for (int mt = 0; mt < 4; mt++) {
        int r0 = rowBase + warpM + mt * 16 + rq;
        #pragma unroll
        for (int nt = 0; nt < 4; nt++) {
            int cc = colBase + warpN + nt * 8 + cq;
            if (r0 < N_NODES) {
                __half2 h = __floats2half2_rn(acc[mt][nt][0], acc[mt][nt][1]);
                *(__half2*)(g_support_h + (size_t)r0 * OUT_F + cc) = h;
            }
            if (r0 + 8 < N_NODES) {
                __half2 h = __floats2half2_rn(acc[mt][nt][2], acc[mt][nt][3]);
                *(__half2*)(g_support_h + (size_t)(r0 + 8) * OUT_F + cc) = h;
            }
        }
    }
}

// ---------------- CSR build --------------------------------------------------
__global__ void hist_kernel(const int* __restrict__ row) {
    int e = blockIdx.x * blockDim.x + threadIdx.x;
    if (e < N_EDGES) atomicAdd(&g_count[row[e]], 1);
}

__global__ __launch_bounds__(1024) void scan1_kernel() {
    __shared__ int ws[32];
    const int t = threadIdx.x, lane = t & 31, w = t >> 5;
    const int i = blockIdx.x * SCAN_B + t;
    int c = (i < N_NODES) ? g_count[i] : 0;
    int incl = c;
    #pragma unroll
    for (int d = 1; d < 32; d <<= 1) {
        int v = __shfl_up_sync(0xffffffffu, incl, d);
        if (lane >= d) incl += v;
    }
    if (lane == 31) ws[w] = incl;
    __syncthreads();
    if (w == 0) {
        int s = ws[lane];
        #pragma unroll
        for (int d = 1; d < 32; d <<= 1) {
            int v = __shfl_up_sync(0xffffffffu, s, d);
            if (lane >= d) s += v;
        }
        ws[lane] = s;
    }
    __syncthreads();
    int off = (w > 0) ? ws[w - 1] : 0;
    if (i < N_NODES) g_start[i] = off + incl - c;
    if (t == SCAN_B - 1) g_bsum[blockIdx.x] = ws[31];
}

__global__ void scan2_kernel() {
    __shared__ int ws[4];
    const int t = threadIdx.x, lane = t & 31, w = t >> 5;
    int c = (t < N_SBLK) ? g_bsum[t] : 0;
    int incl = c;
    #pragma unroll
    for (int d = 1; d < 32; d <<= 1) {
        int v = __shfl_up_sync(0xffffffffu, incl, d);
        if (lane >= d) incl += v;
    }
    if (lane == 31) ws[w] = incl;
    __syncthreads();
    int woff = 0;
    #pragma unroll
    for (int j = 0; j < 4; j++) if (j < w) woff += ws[j];
    if (t < N_SBLK) g_boff[t] = woff + incl - c;
    if (t == 0) g_start[N_NODES] = ws[0] + ws[1] + ws[2] + ws[3];
}

__global__ __launch_bounds__(1024) void scan3_kernel() {
    const int i = blockIdx.x * SCAN_B + threadIdx.x;
    if (i < N_NODES) {
        g_start[i] += g_boff[blockIdx.x];
        g_count[i] = 0;
    }
}

__global__ void scatter_kernel(const int* __restrict__ row,
                               const int* __restrict__ col,
                               const float* __restrict__ val) {
    int e = blockIdx.x * blockDim.x + threadIdx.x;
    if (e < N_EDGES) {
        int r = row[e];
        int p = g_start[r] + atomicAdd(&g_count[r], 1);
        g_col[p] = col[e];
        g_val[p] = val[e];
    }
}

// ---------------- SpMM + ReLU (single pass, fp16 gather, fp32 accumulate) ----
// one row per 32-thread warp; lane covers 8 consecutive cols (uint4 of halves)
__global__ __launch_bounds__(256) void spmm_kernel(float* __restrict__ out) {
    const int row = blockIdx.x * 8 + threadIdx.y;
    if (row >= N_NODES) return;
    const int lane = threadIdx.x;                 // 0..31
    const int s = g_start[row];
    const int e = g_start[row + 1];
    const uint4* __restrict__ sup = (const uint4*)g_support_h;  // 32 uint4 per row

    float acc[8];
    #pragma unroll
    for (int q = 0; q < 8; q++) acc[q] = 0.f;

    auto accum = [&](uint4 x, float v) {
        __half2 h0 = *(__half2*)&x.x;
        __half2 h1 = *(__half2*)&x.y;
        __half2 h2 = *(__half2*)&x.z;
        __half2 h3 = *(__half2*)&x.w;
        float2 f0 = __half22float2(h0);
        float2 f1 = __half22float2(h1);
        float2 f2 = __half22float2(h2);
        float2 f3 = __half22float2(h3);
        acc[0] += v * f0.x; acc[1] += v * f0.y;
        acc[2] += v * f1.x; acc[3] += v * f1.y;
        acc[4] += v * f2.x; acc[5] += v * f2.y;
        acc[6] += v * f3.x; acc[7] += v * f3.y;
    };

    int i = s;
    for (; i + 4 <= e; i += 4) {
        int   c0 = g_col[i],     c1 = g_col[i + 1];
        int   c2 = g_col[i + 2], c3 = g_col[i + 3];
        float v0 = g_val[i],     v1 = g_val[i + 1];
        float v2 = g_val[i + 2], v3 = g_val[i + 3];
        uint4 x0 = __ldg(sup + (size_t)c0 * 32 + lane);
        uint4 x1 = __ldg(sup + (size_t)c1 * 32 + lane);
        uint4 x2 = __ldg(sup + (size_t)c2 * 32 + lane);
        uint4 x3 = __ldg(sup + (size_t)c3 * 32 + lane);
        accum(x0, v0); accum(x1, v1); accum(x2, v2); accum(x3, v3);
    }
    for (; i < e; i++) {
        uint4 x = __ldg(sup + (size_t)g_col[i] * 32 + lane);
        accum(x, g_val[i]);
    }

    #pragma unroll
    for (int q = 0; q < 8; q++) acc[q] = fmaxf(acc[q], 0.f);
    float4* o = (float4*)(out + (size_t)row * OUT_F + lane * 8);
    o[0] = make_float4(acc[0], acc[1], acc[2], acc[3]);
    o[1] = make_float4(acc[4], acc[5], acc[6], acc[7]);
}

// ---------------- launch -----------------------------------------------------
extern "C" void kernel_launch(void* const* d_in, const int* in_sizes, int n_in,
                              void* d_out, int out_size) {
    const float* features = (const float*)d_in[0];
    const float* weight   = (const float*)d_in[1];
    const int*   edge_row = (const int*)d_in[2];
    const int*   edge_col = (const int*)d_in[3];
    const float* edge_val = (const float*)d_in[4];
    float* out = (float*)d_out;

    cudaFuncSetAttribute(gemm_mma_kernel,
                         cudaFuncAttributeMaxDynamicSharedMemorySize, SM_TOTAL);

    bconv_kernel<<<(IN_F * OUT_F + 255) / 256, 256>>>(weight);

    dim3 gemm_grid(OUT_F / 128, (N_NODES + 127) / 128);
    gemm_mma_kernel<<<gemm_grid, 256, SM_TOTAL>>>(features);

    hist_kernel<<<(N_EDGES + 255) / 256, 256>>>(edge_row);
    scan1_kernel<<<N_SBLK, SCAN_B>>>();
    scan2_kernel<<<1, 128>>>();
    scan3_kernel<<<N_SBLK, SCAN_B>>>();
    scatter_kernel<<<(N_EDGES + 255) / 256, 256>>>(edge_row, edge_col, edge_val);

    dim3 spmm_block(32, 8);
    spmm_kernel<<<(N_NODES + 7) / 8, spmm_block>>>(out);

    (void)in_sizes; (void)n_in; (void)out_size;
}